// round 1
// baseline (speedup 1.0000x reference)
#include <cuda_runtime.h>
#include <cuda_bf16.h>
#include <stdint.h>

// ---------------------------------------------------------------------------
// KMeans 1-D, K=256, 10 Lloyd iterations, exact interval-partition algorithm.
// ---------------------------------------------------------------------------

#define NCAP   (1 << 21)       // max N (problem is 2,097,152)
#define NB     16384           // buckets = top 14 bits of sortable key
#define BSHIFT 18              // 32 - 14
#define KC     256
#define FXSCALE 8589934592.0   // 2^33 fixed-point scale (deterministic integer sums)

// -------------------- static device state (no allocations) -----------------
__device__ unsigned int       g_cnt[NB];
__device__ unsigned long long g_bsum[NB];
__device__ unsigned int       g_bstart[NB + 1];
__device__ unsigned long long g_bsumpref[NB + 1];
__device__ unsigned int       g_cursor[NB];
__device__ unsigned int       g_skeys[NCAP];
__device__ float              g_centers[KC];
__device__ float              g_u[KC];      // distinct sorted center values
__device__ int                g_uhead[KC];  // min original index of each run
__device__ int                g_m;          // number of distinct values
__device__ unsigned int       g_T[KC];      // boundary threshold keys
__device__ unsigned int       g_belowCnt[KC];
__device__ unsigned long long g_belowSum[KC];

// -------------------- helpers ----------------------------------------------
__device__ __forceinline__ unsigned int f2k(float f) {
    unsigned int u = __float_as_uint(f);
    return (u & 0x80000000u) ? ~u : (u | 0x80000000u);
}
__device__ __forceinline__ float k2f(unsigned int k) {
    unsigned int u = (k & 0x80000000u) ? (k & 0x7fffffffu) : ~k;
    return __uint_as_float(u);
}
__device__ __forceinline__ long long ffix(float x) {
    return llrint((double)x * FXSCALE);   // exact, order-independent sums
}
// Exactly the reference's f32 comparison: argmin(|x-c|), first index wins ties.
__device__ __forceinline__ bool prefers_left(float x, float cl, float cr, int hl, int hr) {
    float dl = fabsf(x - cl), dr = fabsf(x - cr);
    if (dl < dr) return true;
    if (dl > dr) return false;
    return hl < hr;
}

// -------------------- kernels ----------------------------------------------
__global__ void k_zero() {
    int i = blockIdx.x * blockDim.x + threadIdx.x;
    if (i < NB) { g_cnt[i] = 0u; g_bsum[i] = 0ull; }
}

__global__ void k_hist(const float* __restrict__ x, int n) {
    int stride = gridDim.x * blockDim.x;
    for (int i = blockIdx.x * blockDim.x + threadIdx.x; i < n; i += stride) {
        float v = x[i];
        unsigned int b = f2k(v) >> BSHIFT;
        atomicAdd(&g_cnt[b], 1u);
        atomicAdd(&g_bsum[b], (unsigned long long)ffix(v));
    }
}

__global__ void k_scan() {
    __shared__ unsigned int       s_c[256];
    __shared__ unsigned long long s_s[256];
    int t = threadIdx.x;
    const int PER = NB / 256;
    int base = t * PER;
    unsigned int cs = 0; unsigned long long ss = 0;
    for (int i = 0; i < PER; i++) { cs += g_cnt[base + i]; ss += g_bsum[base + i]; }
    s_c[t] = cs; s_s[t] = ss;
    __syncthreads();
    for (int off = 1; off < 256; off <<= 1) {
        unsigned int c = (t >= off) ? s_c[t - off] : 0u;
        unsigned long long s = (t >= off) ? s_s[t - off] : 0ull;
        __syncthreads();
        s_c[t] += c; s_s[t] += s;
        __syncthreads();
    }
    unsigned int cb = (t == 0) ? 0u : s_c[t - 1];
    unsigned long long sb = (t == 0) ? 0ull : s_s[t - 1];
    for (int i = 0; i < PER; i++) {
        g_bstart[base + i] = cb; g_cursor[base + i] = cb; g_bsumpref[base + i] = sb;
        cb += g_cnt[base + i];   sb += g_bsum[base + i];
    }
    if (t == 255) { g_bstart[NB] = cb; g_bsumpref[NB] = sb; }
}

__global__ void k_scatter(const float* __restrict__ x, int n) {
    int stride = gridDim.x * blockDim.x;
    for (int i = blockIdx.x * blockDim.x + threadIdx.x; i < n; i += stride) {
        unsigned int k = f2k(x[i]);
        unsigned int slot = atomicAdd(&g_cursor[k >> BSHIFT], 1u);
        g_skeys[slot] = k;
    }
}

struct InitIdx { int idx[KC]; };
__global__ void k_init(const float* __restrict__ x, InitIdx p) {
    int t = threadIdx.x;
    g_centers[t] = x[p.idx[t]];
}

// One block, 256 threads: (optional update) -> sort -> dedupe -> thresholds.
__global__ void k_prep(int apply_update, int n) {
    __shared__ unsigned long long s_pair[KC];
    __shared__ float s_val[KC];
    __shared__ int   s_orig[KC];
    __shared__ int   s_flag[KC];
    __shared__ int   s_pos[KC];
    __shared__ float s_u[KC];
    __shared__ int   s_h[KC];
    int t = threadIdx.x;

    if (apply_update) {
        int pm = g_m;
        if (t < pm) {
            unsigned int       c0 = (t == 0) ? 0u   : g_belowCnt[t - 1];
            unsigned int       c1 = (t == pm - 1) ? (unsigned int)n : g_belowCnt[t];
            unsigned long long s0 = (t == 0) ? 0ull : g_belowSum[t - 1];
            unsigned long long s1 = (t == pm - 1) ? g_bsumpref[NB] : g_belowSum[t];
            unsigned int cnt = c1 - c0;
            if (cnt > 0u) {
                long long diff = (long long)(s1 - s0);
                double mean = ((double)diff / FXSCALE) / (double)cnt;
                g_centers[g_uhead[t]] = (float)mean;  // empty clusters keep old center
            }
        }
        __syncthreads();
    }

    float c = g_centers[t];
    s_pair[t] = ((unsigned long long)f2k(c) << 32) | (unsigned int)t;
    __syncthreads();

    // bitonic sort, 256 elems, stable via (key, origIdx) composite
    for (int k = 2; k <= KC; k <<= 1) {
        for (int j = k >> 1; j > 0; j >>= 1) {
            int ixj = t ^ j;
            if (ixj > t) {
                unsigned long long a = s_pair[t], b = s_pair[ixj];
                bool up = ((t & k) == 0);
                if (up ? (a > b) : (a < b)) { s_pair[t] = b; s_pair[ixj] = a; }
            }
            __syncthreads();
        }
    }
    s_val[t]  = k2f((unsigned int)(s_pair[t] >> 32));
    s_orig[t] = (int)(s_pair[t] & 0xffffffffu);
    __syncthreads();

    // distinct-value runs (float compare merges -0/+0); head = min orig index
    s_flag[t] = (t == 0) || (s_val[t] != s_val[t - 1]);
    __syncthreads();
    s_pos[t] = s_flag[t];
    __syncthreads();
    for (int off = 1; off < KC; off <<= 1) {
        int v = (t >= off) ? s_pos[t - off] : 0;
        __syncthreads();
        s_pos[t] += v;
        __syncthreads();
    }
    int m = s_pos[KC - 1];
    if (s_flag[t]) {
        int d = s_pos[t] - 1;
        int mn = s_orig[t];
        for (int q = t + 1; q < KC && !s_flag[q]; q++) mn = min(mn, s_orig[q]);
        s_u[d] = s_val[t]; s_h[d] = mn;
        g_u[d] = s_val[t]; g_uhead[d] = mn;
    }
    if (t == 0) g_m = m;
    __syncthreads();

    // exact flip-point search in key space between adjacent distinct centers
    if (t < m - 1) {
        float cl = s_u[t], cr = s_u[t + 1];
        int   hl = s_h[t], hr = s_h[t + 1];
        unsigned int lo = f2k(cl), hi = f2k(cr);  // pred(lo)=true, pred(hi)=false
        while (hi - lo > 1u) {
            unsigned int mid = lo + ((hi - lo) >> 1);
            if (prefers_left(k2f(mid), cl, cr, hl, hr)) lo = mid; else hi = mid;
        }
        g_T[t] = hi;  // smallest key assigned right
    }
}

// 255 blocks: exact (count, fixed-sum) of keys below threshold j.
__global__ void k_bnd() {
    int j = blockIdx.x;
    int m = g_m;
    if (j >= m - 1) return;
    unsigned int T = g_T[j];
    unsigned int b = T >> BSHIFT;
    unsigned int start = g_bstart[b], end = g_bstart[b + 1];
    int t = threadIdx.x;
    unsigned int c = 0; unsigned long long s = 0;
    for (unsigned int i = start + t; i < end; i += blockDim.x) {
        unsigned int k = g_skeys[i];
        if (k < T) { c++; s += (unsigned long long)ffix(k2f(k)); }
    }
    __shared__ unsigned int       rc[256];
    __shared__ unsigned long long rs[256];
    rc[t] = c; rs[t] = s;
    __syncthreads();
    for (int off = 128; off > 0; off >>= 1) {
        if (t < off) { rc[t] += rc[t + off]; rs[t] += rs[t + off]; }
        __syncthreads();
    }
    if (t == 0) {
        g_belowCnt[j] = g_bstart[b] + rc[0];
        g_belowSum[j] = g_bsumpref[b] + rs[0];
    }
}

// Final remap: per point, lower_bound over distinct centers + exact f32 compare.
__global__ void k_out(const float* __restrict__ x, float* __restrict__ out, int n) {
    __shared__ float s_u[KC];
    __shared__ int   s_h[KC];
    int t = threadIdx.x;
    int m = g_m;
    s_u[t] = (t < m) ? g_u[t] : __int_as_float(0x7f800000);  // +inf pad
    s_h[t] = (t < m) ? g_uhead[t] : 0x7fffffff;
    __syncthreads();
    int stride = gridDim.x * blockDim.x;
    for (int i = blockIdx.x * blockDim.x + t; i < n; i += stride) {
        float v = x[i];
        int p = 0;
        #pragma unroll
        for (int step = 128; step > 0; step >>= 1) {
            int np = p + step;
            if (s_u[np - 1] < v) p = np;
        }
        float res;
        if (p == 0)      res = s_u[0];
        else if (p >= m) res = s_u[m - 1];
        else {
            float cl = s_u[p - 1], cr = s_u[p];
            float dl = fabsf(v - cl), dr = fabsf(v - cr);
            res = (dl < dr) ? cl : (dr < dl) ? cr : ((s_h[p - 1] < s_h[p]) ? cl : cr);
        }
        out[i] = res;
    }
}

// -------------------- host: JAX threefry-2x32 replication -------------------
static inline uint32_t rotl32(uint32_t x, int d) { return (x << d) | (x >> (32 - d)); }
static void tf2x32(uint32_t k0, uint32_t k1, uint32_t x0, uint32_t x1,
                   uint32_t* o0, uint32_t* o1) {
    uint32_t ks[3] = { k0, k1, (uint32_t)(k0 ^ k1 ^ 0x1BD11BDAu) };
    uint32_t v0 = x0 + ks[0], v1 = x1 + ks[1];
    static const int R[2][4] = { {13, 15, 26, 6}, {17, 29, 16, 24} };
    for (int g = 0; g < 5; g++) {
        const int* r = R[g & 1];
        for (int i = 0; i < 4; i++) { v0 += v1; v1 = rotl32(v1, r[i]); v1 ^= v0; }
        v0 += ks[(g + 1) % 3];
        v1 += ks[(g + 2) % 3] + (uint32_t)(g + 1);
    }
    *o0 = v0; *o1 = v1;
}

extern "C" void kernel_launch(void* const* d_in, const int* in_sizes, int n_in,
                              void* d_out, int out_size) {
    const float* x = (const float*)d_in[0];
    float* out = (float*)d_out;
    int n = in_sizes[0];

    // randint(key(42), (256,), 0, n) under jax_threefry_partitionable=True:
    //   split: key_i = threefry(key, hi=0, lo=i); random_bits: bits1^bits2
    //   offset = ((hi%span)*mult + lo%span) % span, mult = (65536%span)^2 wrap32 % span
    InitIdx p;
    {
        uint32_t span = (uint32_t)n;
        uint32_t k1a, k1b, k2a, k2b;
        tf2x32(0u, 42u, 0u, 0u, &k1a, &k1b);  // split -> key 0 (higher bits)
        tf2x32(0u, 42u, 0u, 1u, &k2a, &k2b);  // split -> key 1 (lower bits)
        uint32_t m1 = 65536u % span;
        uint32_t mult = ((uint32_t)(m1 * m1)) % span;  // uint32 wrap then rem
        for (int i = 0; i < KC; i++) {
            uint32_t h1, h2, l1, l2;
            tf2x32(k1a, k1b, 0u, (uint32_t)i, &h1, &h2);
            tf2x32(k2a, k2b, 0u, (uint32_t)i, &l1, &l2);
            uint32_t hb = h1 ^ h2, lb = l1 ^ l2;
            uint32_t off = ((uint32_t)((hb % span) * mult) + (lb % span)) % span;
            p.idx[i] = (int)off;
        }
    }

    k_zero<<<(NB + 255) / 256, 256>>>();
    k_hist<<<1024, 256>>>(x, n);
    k_scan<<<1, 256>>>();
    k_scatter<<<1024, 256>>>(x, n);
    k_init<<<1, 256>>>(x, p);
    for (int it = 0; it < 10; it++) {
        k_prep<<<1, 256>>>(it > 0 ? 1 : 0, n);
        k_bnd<<<KC - 1, 256>>>();
    }
    k_prep<<<1, 256>>>(1, n);   // apply 10th update + final sort/dedupe
    k_out<<<1024, 256>>>(x, out, n);
}

// round 4
// speedup vs baseline: 2.6942x; 2.6942x over previous
#include <cuda_runtime.h>
#include <cuda_bf16.h>
#include <stdint.h>

// ---------------------------------------------------------------------------
// KMeans 1-D, K=256, 10 Lloyd iterations, interval-partition algorithm.
// R2: atomic-free global hist/scatter (per-block smem histograms + hierarchical
//     scan providing per-block scatter bases), packed u64 count+sum atomics,
//     4-way split boundary scans, float4 vectorization.
// ---------------------------------------------------------------------------

#define NCAP   (1 << 21)
#define NB     4096            // buckets = top 12 bits of sortable key
#define BSHIFT 20              // 32 - 12
#define KC     256
#define HB     148             // hist/scatter grid (1 block per SM)
#define HT     512             // hist/scatter block size
#define SPLIT  4               // sub-blocks per boundary scan
#define FXS    16384.0f        // 2^14 fixed-point scale

// -------------------- static device state (no allocations) -----------------
__device__ unsigned long long g_blkhist[HB * NB];   // packed (cnt<<48)+biased-sum
__device__ unsigned int       g_blkbase[HB * NB];   // per-block scatter base
__device__ unsigned int       g_bstart[NB + 1];
__device__ long long          g_bsumpref[NB + 1];
__device__ unsigned int       g_ctot[16];
__device__ long long          g_stot[16];
__device__ unsigned int       g_coff[16];
__device__ long long          g_soff[16];
__device__ unsigned int       g_skeys[NCAP];
__device__ float              g_centers[KC];
__device__ float              g_u[KC];
__device__ int                g_uhead[KC];
__device__ int                g_m;
__device__ unsigned int       g_T[KC];
__device__ unsigned int       g_belowCnt[KC];
__device__ unsigned long long g_belowSum[KC];       // two's-complement wrap

// -------------------- helpers ----------------------------------------------
__device__ __forceinline__ unsigned int f2k(float f) {
    unsigned int u = __float_as_uint(f);
    return (u & 0x80000000u) ? ~u : (u | 0x80000000u);
}
__device__ __forceinline__ float k2f(unsigned int k) {
    unsigned int u = (k & 0x80000000u) ? (k & 0x7fffffffu) : ~k;
    return __uint_as_float(u);
}
__device__ __forceinline__ long long ffix(float x) {
    return llrintf(x * FXS);   // consistent everywhere -> exact integer sums
}
__device__ __forceinline__ bool prefers_left(float x, float cl, float cr, int hl, int hr) {
    float dl = fabsf(x - cl), dr = fabsf(x - cr);
    if (dl < dr) return true;
    if (dl > dr) return false;
    return hl < hr;
}

// -------------------- hist: per-block smem packed histogram ----------------
__global__ void __launch_bounds__(HT) k_hist(const float* __restrict__ x, int n) {
    __shared__ unsigned long long s_h[NB];   // 32KB
    int t = threadIdx.x;
    for (int i = t; i < NB; i += HT) s_h[i] = 0ull;
    __syncthreads();
    const float4* x4 = (const float4*)x;
    int n4 = n >> 2;
    int stride = gridDim.x * HT;
    for (int i = blockIdx.x * HT + t; i < n4; i += stride) {
        float4 v = x4[i];
        float vv[4] = { v.x, v.y, v.z, v.w };
        #pragma unroll
        for (int j = 0; j < 4; j++) {
            unsigned int b = f2k(vv[j]) >> BSHIFT;
            long long f = ffix(vv[j]);
            unsigned long long add = (1ull << 48) + (unsigned long long)(unsigned int)(f + (1LL << 31));
            atomicAdd(&s_h[b], add);
        }
    }
    if (blockIdx.x == 0 && t == 0) {
        for (int i = n4 << 2; i < n; i++) {
            unsigned int b = f2k(x[i]) >> BSHIFT;
            long long f = ffix(x[i]);
            unsigned long long add = (1ull << 48) + (unsigned long long)(unsigned int)(f + (1LL << 31));
            atomicAdd(&s_h[b], add);
        }
    }
    __syncthreads();
    unsigned long long* dst = &g_blkhist[blockIdx.x * NB];
    for (int i = t; i < NB; i += HT) dst[i] = s_h[i];
}

// -------------------- scan A: per-bucket totals + per-block bases ----------
__global__ void k_scanA() {
    __shared__ unsigned int s_c[256];
    __shared__ long long    s_s[256];
    int t = threadIdx.x;
    int b = blockIdx.x * 256 + t;
    unsigned int cnt = 0; long long sum = 0;
    for (int blk = 0; blk < HB; blk++) {
        unsigned long long v = g_blkhist[blk * NB + b];
        g_blkbase[blk * NB + b] = cnt;
        unsigned int c = (unsigned int)(v >> 48);
        long long sf = (long long)(v & ((1ull << 48) - 1)) - ((long long)c << 31);
        cnt += c; sum += sf;
    }
    s_c[t] = cnt; s_s[t] = sum;
    __syncthreads();
    for (int off = 1; off < 256; off <<= 1) {
        unsigned int c = (t >= off) ? s_c[t - off] : 0u;
        long long    s = (t >= off) ? s_s[t - off] : 0ll;
        __syncthreads();
        s_c[t] += c; s_s[t] += s;
        __syncthreads();
    }
    g_bstart[b]   = s_c[t] - cnt;   // chunk-local exclusive
    g_bsumpref[b] = s_s[t] - sum;
    if (t == 255) { g_ctot[blockIdx.x] = s_c[255]; g_stot[blockIdx.x] = s_s[255]; }
}

__global__ void k_scanB() {
    unsigned int c = 0; long long s = 0;
    for (int i = 0; i < NB / 256; i++) {
        g_coff[i] = c; g_soff[i] = s;
        c += g_ctot[i]; s += g_stot[i];
    }
    g_bstart[NB] = c; g_bsumpref[NB] = s;
}

__global__ void k_scanC() {
    int b = blockIdx.x * 256 + threadIdx.x;
    g_bstart[b]   += g_coff[blockIdx.x];
    g_bsumpref[b] += g_soff[blockIdx.x];
}

// -------------------- scatter: no global atomics ---------------------------
__global__ void __launch_bounds__(HT) k_scatter(const float* __restrict__ x, int n) {
    __shared__ unsigned int s_cur[NB];   // 16KB
    int t = threadIdx.x;
    for (int i = t; i < NB; i += HT) s_cur[i] = 0u;
    __syncthreads();
    const unsigned int* base = &g_blkbase[blockIdx.x * NB];
    const float4* x4 = (const float4*)x;
    int n4 = n >> 2;
    int stride = gridDim.x * HT;
    for (int i = blockIdx.x * HT + t; i < n4; i += stride) {
        float4 v = x4[i];
        float vv[4] = { v.x, v.y, v.z, v.w };
        #pragma unroll
        for (int j = 0; j < 4; j++) {
            unsigned int k = f2k(vv[j]);
            unsigned int b = k >> BSHIFT;
            unsigned int r = atomicAdd(&s_cur[b], 1u);
            g_skeys[g_bstart[b] + base[b] + r] = k;
        }
    }
    if (blockIdx.x == 0 && t == 0) {
        for (int i = n4 << 2; i < n; i++) {
            unsigned int k = f2k(x[i]);
            unsigned int b = k >> BSHIFT;
            unsigned int r = atomicAdd(&s_cur[b], 1u);
            g_skeys[g_bstart[b] + base[b] + r] = k;
        }
    }
}

// -------------------- init -------------------------------------------------
struct InitIdx { int idx[KC]; };
__global__ void k_init(const float* __restrict__ x, InitIdx p) {
    g_centers[threadIdx.x] = x[p.idx[threadIdx.x]];
}

// ------- prep: (update) -> sort -> dedupe -> thresholds -> zero accum ------
__global__ void k_prep(int apply_update, int n) {
    __shared__ unsigned long long s_pair[KC];
    __shared__ float s_val[KC];
    __shared__ int   s_orig[KC];
    __shared__ int   s_flag[KC];
    __shared__ int   s_pos[KC];
    __shared__ float s_u[KC];
    __shared__ int   s_h[KC];
    int t = threadIdx.x;

    if (apply_update) {
        int pm = g_m;
        if (t < pm) {
            unsigned int c0 = (t == 0) ? 0u : g_belowCnt[t - 1];
            unsigned int c1 = (t == pm - 1) ? (unsigned int)n : g_belowCnt[t];
            long long s0 = (t == 0) ? 0ll : (long long)g_belowSum[t - 1];
            long long s1 = (t == pm - 1) ? g_bsumpref[NB] : (long long)g_belowSum[t];
            unsigned int cnt = c1 - c0;
            if (cnt > 0u) {
                double mean = ((double)(s1 - s0) / (double)FXS) / (double)cnt;
                g_centers[g_uhead[t]] = (float)mean;
            }
        }
        __syncthreads();
    }

    float c = g_centers[t];
    s_pair[t] = ((unsigned long long)f2k(c) << 32) | (unsigned int)t;
    __syncthreads();

    for (int k = 2; k <= KC; k <<= 1) {
        for (int j = k >> 1; j > 0; j >>= 1) {
            int ixj = t ^ j;
            if (ixj > t) {
                unsigned long long a = s_pair[t], b = s_pair[ixj];
                bool up = ((t & k) == 0);
                if (up ? (a > b) : (a < b)) { s_pair[t] = b; s_pair[ixj] = a; }
            }
            __syncthreads();
        }
    }
    s_val[t]  = k2f((unsigned int)(s_pair[t] >> 32));
    s_orig[t] = (int)(s_pair[t] & 0xffffffffu);
    __syncthreads();

    s_flag[t] = (t == 0) || (s_val[t] != s_val[t - 1]);
    __syncthreads();
    s_pos[t] = s_flag[t];
    __syncthreads();
    for (int off = 1; off < KC; off <<= 1) {
        int v = (t >= off) ? s_pos[t - off] : 0;
        __syncthreads();
        s_pos[t] += v;
        __syncthreads();
    }
    int m = s_pos[KC - 1];
    if (s_flag[t]) {
        int d = s_pos[t] - 1;
        int mn = s_orig[t];
        for (int q = t + 1; q < KC && !s_flag[q]; q++) mn = min(mn, s_orig[q]);
        s_u[d] = s_val[t]; s_h[d] = mn;
        g_u[d] = s_val[t]; g_uhead[d] = mn;
    }
    if (t == 0) g_m = m;
    __syncthreads();

    if (t < m - 1) {
        float cl = s_u[t], cr = s_u[t + 1];
        int   hl = s_h[t], hr = s_h[t + 1];
        unsigned int lo = f2k(cl), hi = f2k(cr);
        while (hi - lo > 1u) {
            unsigned int mid = lo + ((hi - lo) >> 1);
            if (prefers_left(k2f(mid), cl, cr, hl, hr)) lo = mid; else hi = mid;
        }
        g_T[t] = hi;
    }
    // zero accumulators for the next boundary pass (after values consumed)
    g_belowCnt[t] = 0u;
    g_belowSum[t] = 0ull;
}

// ------- bnd: SPLIT sub-blocks per threshold, atomic integer partials ------
__global__ void k_bnd() {
    int j = blockIdx.x / SPLIT;
    int s = blockIdx.x % SPLIT;
    int m = g_m;
    if (j >= m - 1) return;
    unsigned int T = g_T[j];
    unsigned int b = T >> BSHIFT;
    unsigned int start = g_bstart[b], end = g_bstart[b + 1];
    unsigned int len = end - start;
    unsigned int lo = start + (unsigned int)(((unsigned long long)len * s) / SPLIT);
    unsigned int hi = start + (unsigned int)(((unsigned long long)len * (s + 1)) / SPLIT);
    int t = threadIdx.x;
    unsigned int c = 0; long long sum = 0;
    for (unsigned int i = lo + t; i < hi; i += blockDim.x) {
        unsigned int k = g_skeys[i];
        if (k < T) { c++; sum += ffix(k2f(k)); }
    }
    __shared__ unsigned int rc[256];
    __shared__ long long    rs[256];
    rc[t] = c; rs[t] = sum;
    __syncthreads();
    for (int off = 128; off > 0; off >>= 1) {
        if (t < off) { rc[t] += rc[t + off]; rs[t] += rs[t + off]; }
        __syncthreads();
    }
    if (t == 0) {
        unsigned int addc = rc[0] + (s == 0 ? g_bstart[b] : 0u);
        long long    adds = rs[0] + (s == 0 ? g_bsumpref[b] : 0ll);
        atomicAdd(&g_belowCnt[j], addc);
        atomicAdd(&g_belowSum[j], (unsigned long long)adds);
    }
}

// -------------------- final remap (float4) ---------------------------------
__global__ void k_out(const float* __restrict__ x, float* __restrict__ out, int n) {
    __shared__ float s_u[KC];
    __shared__ int   s_h[KC];
    int t = threadIdx.x;
    int m = g_m;
    s_u[t] = (t < m) ? g_u[t] : __int_as_float(0x7f800000);
    s_h[t] = (t < m) ? g_uhead[t] : 0x7fffffff;
    __syncthreads();
    const float4* x4 = (const float4*)x;
    float4* o4 = (float4*)out;
    int n4 = n >> 2;
    int stride = gridDim.x * blockDim.x;
    for (int i = blockIdx.x * blockDim.x + t; i < n4; i += stride) {
        float4 v = x4[i];
        float vv[4] = { v.x, v.y, v.z, v.w };
        float rr[4];
        #pragma unroll
        for (int j = 0; j < 4; j++) {
            float val = vv[j];
            int p = 0;
            #pragma unroll
            for (int step = 128; step > 0; step >>= 1) {
                int np = p + step;
                if (s_u[np - 1] < val) p = np;
            }
            float res;
            if (p == 0)      res = s_u[0];
            else if (p >= m) res = s_u[m - 1];
            else {
                float cl = s_u[p - 1], cr = s_u[p];
                float dl = fabsf(val - cl), dr = fabsf(val - cr);
                res = (dl < dr) ? cl : (dr < dl) ? cr : ((s_h[p - 1] < s_h[p]) ? cl : cr);
            }
            rr[j] = res;
        }
        o4[i] = make_float4(rr[0], rr[1], rr[2], rr[3]);
    }
    if (blockIdx.x == 0 && t == 0) {
        for (int i = n4 << 2; i < n; i++) {
            float val = x[i];
            int p = 0;
            for (int step = 128; step > 0; step >>= 1) {
                int np = p + step;
                if (s_u[np - 1] < val) p = np;
            }
            float res;
            if (p == 0)      res = s_u[0];
            else if (p >= m) res = s_u[m - 1];
            else {
                float cl = s_u[p - 1], cr = s_u[p];
                float dl = fabsf(val - cl), dr = fabsf(val - cr);
                res = (dl < dr) ? cl : (dr < dl) ? cr : ((s_h[p - 1] < s_h[p]) ? cl : cr);
            }
            out[i] = res;
        }
    }
}

// -------------------- host: JAX threefry-2x32 replication -------------------
static inline uint32_t rotl32(uint32_t x, int d) { return (x << d) | (x >> (32 - d)); }
static void tf2x32(uint32_t k0, uint32_t k1, uint32_t x0, uint32_t x1,
                   uint32_t* o0, uint32_t* o1) {
    uint32_t ks[3] = { k0, k1, (uint32_t)(k0 ^ k1 ^ 0x1BD11BDAu) };
    uint32_t v0 = x0 + ks[0], v1 = x1 + ks[1];
    static const int R[2][4] = { {13, 15, 26, 6}, {17, 29, 16, 24} };
    for (int g = 0; g < 5; g++) {
        const int* r = R[g & 1];
        for (int i = 0; i < 4; i++) { v0 += v1; v1 = rotl32(v1, r[i]); v1 ^= v0; }
        v0 += ks[(g + 1) % 3];
        v1 += ks[(g + 2) % 3] + (uint32_t)(g + 1);
    }
    *o0 = v0; *o1 = v1;
}

extern "C" void kernel_launch(void* const* d_in, const int* in_sizes, int n_in,
                              void* d_out, int out_size) {
    const float* x = (const float*)d_in[0];
    float* out = (float*)d_out;
    int n = in_sizes[0];

    InitIdx p;
    {
        uint32_t span = (uint32_t)n;
        uint32_t k1a, k1b, k2a, k2b;
        tf2x32(0u, 42u, 0u, 0u, &k1a, &k1b);
        tf2x32(0u, 42u, 0u, 1u, &k2a, &k2b);
        uint32_t m1 = 65536u % span;
        uint32_t mult = ((uint32_t)(m1 * m1)) % span;
        for (int i = 0; i < KC; i++) {
            uint32_t h1, h2, l1, l2;
            tf2x32(k1a, k1b, 0u, (uint32_t)i, &h1, &h2);
            tf2x32(k2a, k2b, 0u, (uint32_t)i, &l1, &l2);
            uint32_t hb = h1 ^ h2, lb = l1 ^ l2;
            uint32_t off = ((uint32_t)((hb % span) * mult) + (lb % span)) % span;
            p.idx[i] = (int)off;
        }
    }

    k_hist<<<HB, HT>>>(x, n);
    k_scanA<<<NB / 256, 256>>>();
    k_scanB<<<1, 1>>>();
    k_scanC<<<NB / 256, 256>>>();
    k_scatter<<<HB, HT>>>(x, n);
    k_init<<<1, 256>>>(x, p);
    for (int it = 0; it < 10; it++) {
        k_prep<<<1, 256>>>(it > 0 ? 1 : 0, n);
        k_bnd<<<(KC - 1) * SPLIT, 256>>>();
    }
    k_prep<<<1, 256>>>(1, n);
    k_out<<<1024, 256>>>(x, out, n);
}

// round 5
// speedup vs baseline: 4.3490x; 1.6142x over previous
#include <cuda_runtime.h>
#include <cuda_bf16.h>
#include <stdint.h>

// ---------------------------------------------------------------------------
// KMeans 1-D, K=256, 10 Lloyd iterations, interval-partition algorithm.
// R5: 2^20 fine buckets (hot bucket ~300 elems) -> global packed-u64 hist
//     atomics, per-bucket cursor atomics, O(300)-element boundary scans with
//     direct (non-atomic) result stores.
// ---------------------------------------------------------------------------

#define NCAP   (1 << 21)
#define NB     (1 << 20)       // buckets = top 20 bits of sortable key
#define BSHIFT 12              // 32 - 20
#define KC     256
#define CHUNK  1024            // buckets per scan block
#define SCB    (NB / CHUNK)    // 1024 scan blocks
#define FXS    16384.0f        // 2^14 fixed-point scale
#define M48    ((1ull << 48) - 1)

// -------------------- static device state (no allocations) -----------------
__device__ unsigned long long g_hist[NB];         // packed (cnt<<48)+biased-sum
__device__ unsigned int       g_bstart[NB + 1];
__device__ long long          g_bsumpref[NB + 1];
__device__ unsigned int       g_cursor[NB];
__device__ unsigned int       g_ctot[SCB];
__device__ long long          g_stot[SCB];
__device__ unsigned int       g_coff[SCB];
__device__ long long          g_soff[SCB];
__device__ unsigned int       g_skeys[NCAP];
__device__ float              g_centers[KC];
__device__ float              g_u[KC];
__device__ int                g_uhead[KC];
__device__ int                g_m;
__device__ unsigned int       g_T[KC];
__device__ unsigned int       g_belowCnt[KC];
__device__ long long          g_belowSum[KC];

// -------------------- helpers ----------------------------------------------
__device__ __forceinline__ unsigned int f2k(float f) {
    unsigned int u = __float_as_uint(f);
    return (u & 0x80000000u) ? ~u : (u | 0x80000000u);
}
__device__ __forceinline__ float k2f(unsigned int k) {
    unsigned int u = (k & 0x80000000u) ? (k & 0x7fffffffu) : ~k;
    return __uint_as_float(u);
}
__device__ __forceinline__ long long ffix(float x) {
    return llrintf(x * FXS);
}
__device__ __forceinline__ bool prefers_left(float x, float cl, float cr, int hl, int hr) {
    float dl = fabsf(x - cl), dr = fabsf(x - cr);
    if (dl < dr) return true;
    if (dl > dr) return false;
    return hl < hr;
}

// -------------------- clear ------------------------------------------------
__global__ void k_clear() {
    int stride = gridDim.x * blockDim.x;
    for (int i = blockIdx.x * blockDim.x + threadIdx.x; i < NB; i += stride)
        g_hist[i] = 0ull;
}

// -------------------- hist: global packed atomics --------------------------
__global__ void __launch_bounds__(256) k_hist(const float* __restrict__ x, int n) {
    const float4* x4 = (const float4*)x;
    int n4 = n >> 2;
    int stride = gridDim.x * blockDim.x;
    for (int i = blockIdx.x * blockDim.x + threadIdx.x; i < n4; i += stride) {
        float4 v = x4[i];
        float vv[4] = { v.x, v.y, v.z, v.w };
        #pragma unroll
        for (int j = 0; j < 4; j++) {
            unsigned int b = f2k(vv[j]) >> BSHIFT;
            long long f = ffix(vv[j]);
            unsigned long long add = (1ull << 48)
                + (unsigned long long)(unsigned int)(f + (1LL << 31));
            atomicAdd(&g_hist[b], add);
        }
    }
    if (blockIdx.x == 0 && threadIdx.x == 0) {
        for (int i = n4 << 2; i < n; i++) {
            unsigned int b = f2k(x[i]) >> BSHIFT;
            long long f = ffix(x[i]);
            unsigned long long add = (1ull << 48)
                + (unsigned long long)(unsigned int)(f + (1LL << 31));
            atomicAdd(&g_hist[b], add);
        }
    }
}

// -------------------- scan A: per-chunk totals ------------------------------
__global__ void __launch_bounds__(256) k_scanA() {
    __shared__ unsigned int rc[256];
    __shared__ long long    rs[256];
    int t = threadIdx.x;
    int base = blockIdx.x * CHUNK + t * 4;
    unsigned int c = 0; long long s = 0;
    #pragma unroll
    for (int k = 0; k < 4; k++) {
        unsigned long long v = g_hist[base + k];
        unsigned int cnt = (unsigned int)(v >> 48);
        long long sf = (long long)(v & M48) - ((long long)cnt << 31);
        c += cnt; s += sf;
    }
    rc[t] = c; rs[t] = s;
    __syncthreads();
    for (int off = 128; off > 0; off >>= 1) {
        if (t < off) { rc[t] += rc[t + off]; rs[t] += rs[t + off]; }
        __syncthreads();
    }
    if (t == 0) { g_ctot[blockIdx.x] = rc[0]; g_stot[blockIdx.x] = rs[0]; }
}

// -------------------- scan B: scan 1024 chunk totals ------------------------
__global__ void __launch_bounds__(1024) k_scanB() {
    __shared__ unsigned int s_c[1024];
    __shared__ long long    s_s[1024];
    int t = threadIdx.x;
    unsigned int c = g_ctot[t];
    long long    s = g_stot[t];
    s_c[t] = c; s_s[t] = s;
    __syncthreads();
    for (int off = 1; off < 1024; off <<= 1) {
        unsigned int cc = (t >= off) ? s_c[t - off] : 0u;
        long long    ss = (t >= off) ? s_s[t - off] : 0ll;
        __syncthreads();
        s_c[t] += cc; s_s[t] += ss;
        __syncthreads();
    }
    g_coff[t] = s_c[t] - c;   // exclusive
    g_soff[t] = s_s[t] - s;
    if (t == 1023) { g_bstart[NB] = s_c[1023]; g_bsumpref[NB] = s_s[1023]; }
}

// -------------------- scan C: final prefix + cursor init --------------------
__global__ void __launch_bounds__(256) k_scanC() {
    __shared__ unsigned int s_c[256];
    __shared__ long long    s_s[256];
    int t = threadIdx.x;
    int base = blockIdx.x * CHUNK + t * 4;
    unsigned int cnt4[4]; long long sum4[4];
    unsigned int c = 0; long long s = 0;
    #pragma unroll
    for (int k = 0; k < 4; k++) {
        unsigned long long v = g_hist[base + k];
        cnt4[k] = (unsigned int)(v >> 48);
        sum4[k] = (long long)(v & M48) - ((long long)cnt4[k] << 31);
        c += cnt4[k]; s += sum4[k];
    }
    s_c[t] = c; s_s[t] = s;
    __syncthreads();
    for (int off = 1; off < 256; off <<= 1) {
        unsigned int cc = (t >= off) ? s_c[t - off] : 0u;
        long long    ss = (t >= off) ? s_s[t - off] : 0ll;
        __syncthreads();
        s_c[t] += cc; s_s[t] += ss;
        __syncthreads();
    }
    unsigned int runc = g_coff[blockIdx.x] + s_c[t] - c;
    long long    runs = g_soff[blockIdx.x] + s_s[t] - s;
    #pragma unroll
    for (int k = 0; k < 4; k++) {
        g_bstart[base + k]   = runc;
        g_cursor[base + k]   = runc;
        g_bsumpref[base + k] = runs;
        runc += cnt4[k]; runs += sum4[k];
    }
}

// -------------------- scatter: per-bucket global cursors --------------------
__global__ void __launch_bounds__(256) k_scatter(const float* __restrict__ x, int n) {
    const float4* x4 = (const float4*)x;
    int n4 = n >> 2;
    int stride = gridDim.x * blockDim.x;
    for (int i = blockIdx.x * blockDim.x + threadIdx.x; i < n4; i += stride) {
        float4 v = x4[i];
        float vv[4] = { v.x, v.y, v.z, v.w };
        #pragma unroll
        for (int j = 0; j < 4; j++) {
            unsigned int k = f2k(vv[j]);
            unsigned int slot = atomicAdd(&g_cursor[k >> BSHIFT], 1u);
            g_skeys[slot] = k;
        }
    }
    if (blockIdx.x == 0 && threadIdx.x == 0) {
        for (int i = n4 << 2; i < n; i++) {
            unsigned int k = f2k(x[i]);
            unsigned int slot = atomicAdd(&g_cursor[k >> BSHIFT], 1u);
            g_skeys[slot] = k;
        }
    }
}

// -------------------- init -------------------------------------------------
struct InitIdx { int idx[KC]; };
__global__ void k_init(const float* __restrict__ x, InitIdx p) {
    g_centers[threadIdx.x] = x[p.idx[threadIdx.x]];
}

// ------- prep: (update) -> sort -> dedupe -> thresholds --------------------
__global__ void k_prep(int apply_update, int n) {
    __shared__ unsigned long long s_pair[KC];
    __shared__ float s_val[KC];
    __shared__ int   s_orig[KC];
    __shared__ int   s_flag[KC];
    __shared__ int   s_pos[KC];
    __shared__ float s_u[KC];
    __shared__ int   s_h[KC];
    int t = threadIdx.x;

    if (apply_update) {
        int pm = g_m;
        if (t < pm) {
            unsigned int c0 = (t == 0) ? 0u : g_belowCnt[t - 1];
            unsigned int c1 = (t == pm - 1) ? (unsigned int)n : g_belowCnt[t];
            long long s0 = (t == 0) ? 0ll : g_belowSum[t - 1];
            long long s1 = (t == pm - 1) ? g_bsumpref[NB] : g_belowSum[t];
            unsigned int cnt = c1 - c0;
            if (cnt > 0u) {
                double mean = ((double)(s1 - s0) / (double)FXS) / (double)cnt;
                g_centers[g_uhead[t]] = (float)mean;
            }
        }
        __syncthreads();
    }

    float c = g_centers[t];
    s_pair[t] = ((unsigned long long)f2k(c) << 32) | (unsigned int)t;
    __syncthreads();

    for (int k = 2; k <= KC; k <<= 1) {
        for (int j = k >> 1; j > 0; j >>= 1) {
            int ixj = t ^ j;
            if (ixj > t) {
                unsigned long long a = s_pair[t], b = s_pair[ixj];
                bool up = ((t & k) == 0);
                if (up ? (a > b) : (a < b)) { s_pair[t] = b; s_pair[ixj] = a; }
            }
            __syncthreads();
        }
    }
    s_val[t]  = k2f((unsigned int)(s_pair[t] >> 32));
    s_orig[t] = (int)(s_pair[t] & 0xffffffffu);
    __syncthreads();

    s_flag[t] = (t == 0) || (s_val[t] != s_val[t - 1]);
    __syncthreads();
    s_pos[t] = s_flag[t];
    __syncthreads();
    for (int off = 1; off < KC; off <<= 1) {
        int v = (t >= off) ? s_pos[t - off] : 0;
        __syncthreads();
        s_pos[t] += v;
        __syncthreads();
    }
    int m = s_pos[KC - 1];
    if (s_flag[t]) {
        int d = s_pos[t] - 1;
        int mn = s_orig[t];
        for (int q = t + 1; q < KC && !s_flag[q]; q++) mn = min(mn, s_orig[q]);
        s_u[d] = s_val[t]; s_h[d] = mn;
        g_u[d] = s_val[t]; g_uhead[d] = mn;
    }
    if (t == 0) g_m = m;
    __syncthreads();

    if (t < m - 1) {
        float cl = s_u[t], cr = s_u[t + 1];
        int   hl = s_h[t], hr = s_h[t + 1];
        unsigned int lo = f2k(cl), hi = f2k(cr);
        while (hi - lo > 1u) {
            unsigned int mid = lo + ((hi - lo) >> 1);
            if (prefers_left(k2f(mid), cl, cr, hl, hr)) lo = mid; else hi = mid;
        }
        g_T[t] = hi;
    }
}

// ------- bnd: one block per threshold, ~300-element residual scan ----------
__global__ void __launch_bounds__(128) k_bnd() {
    int j = blockIdx.x;
    int m = g_m;
    if (j >= m - 1) return;
    unsigned int T = g_T[j];
    unsigned int b = T >> BSHIFT;
    unsigned int start = g_bstart[b], end = g_bstart[b + 1];
    int t = threadIdx.x;
    unsigned int c = 0; long long s = 0;
    for (unsigned int i = start + t; i < end; i += 128) {
        unsigned int k = g_skeys[i];
        if (k < T) { c++; s += ffix(k2f(k)); }
    }
    __shared__ unsigned int rc[128];
    __shared__ long long    rs[128];
    rc[t] = c; rs[t] = s;
    __syncthreads();
    for (int off = 64; off > 0; off >>= 1) {
        if (t < off) { rc[t] += rc[t + off]; rs[t] += rs[t + off]; }
        __syncthreads();
    }
    if (t == 0) {
        g_belowCnt[j] = g_bstart[b] + rc[0];
        g_belowSum[j] = g_bsumpref[b] + rs[0];
    }
}

// -------------------- final remap (float4) ---------------------------------
__global__ void __launch_bounds__(256) k_out(const float* __restrict__ x,
                                             float* __restrict__ out, int n) {
    __shared__ float s_u[KC];
    __shared__ int   s_h[KC];
    int t = threadIdx.x;
    int m = g_m;
    s_u[t] = (t < m) ? g_u[t] : __int_as_float(0x7f800000);
    s_h[t] = (t < m) ? g_uhead[t] : 0x7fffffff;
    __syncthreads();
    const float4* x4 = (const float4*)x;
    float4* o4 = (float4*)out;
    int n4 = n >> 2;
    int stride = gridDim.x * blockDim.x;
    for (int i = blockIdx.x * blockDim.x + t; i < n4; i += stride) {
        float4 v = x4[i];
        float vv[4] = { v.x, v.y, v.z, v.w };
        float rr[4];
        #pragma unroll
        for (int j = 0; j < 4; j++) {
            float val = vv[j];
            int p = 0;
            #pragma unroll
            for (int step = 128; step > 0; step >>= 1) {
                int np = p + step;
                if (s_u[np - 1] < val) p = np;
            }
            float res;
            if (p == 0)      res = s_u[0];
            else if (p >= m) res = s_u[m - 1];
            else {
                float cl = s_u[p - 1], cr = s_u[p];
                float dl = fabsf(val - cl), dr = fabsf(val - cr);
                res = (dl < dr) ? cl : (dr < dl) ? cr : ((s_h[p - 1] < s_h[p]) ? cl : cr);
            }
            rr[j] = res;
        }
        o4[i] = make_float4(rr[0], rr[1], rr[2], rr[3]);
    }
    if (blockIdx.x == 0 && t == 0) {
        for (int i = n4 << 2; i < n; i++) {
            float val = x[i];
            int p = 0;
            for (int step = 128; step > 0; step >>= 1) {
                int np = p + step;
                if (s_u[np - 1] < val) p = np;
            }
            float res;
            if (p == 0)      res = s_u[0];
            else if (p >= m) res = s_u[m - 1];
            else {
                float cl = s_u[p - 1], cr = s_u[p];
                float dl = fabsf(val - cl), dr = fabsf(val - cr);
                res = (dl < dr) ? cl : (dr < dl) ? cr : ((s_h[p - 1] < s_h[p]) ? cl : cr);
            }
            out[i] = res;
        }
    }
}

// -------------------- host: JAX threefry-2x32 replication -------------------
static inline uint32_t rotl32(uint32_t x, int d) { return (x << d) | (x >> (32 - d)); }
static void tf2x32(uint32_t k0, uint32_t k1, uint32_t x0, uint32_t x1,
                   uint32_t* o0, uint32_t* o1) {
    uint32_t ks[3] = { k0, k1, (uint32_t)(k0 ^ k1 ^ 0x1BD11BDAu) };
    uint32_t v0 = x0 + ks[0], v1 = x1 + ks[1];
    static const int R[2][4] = { {13, 15, 26, 6}, {17, 29, 16, 24} };
    for (int g = 0; g < 5; g++) {
        const int* r = R[g & 1];
        for (int i = 0; i < 4; i++) { v0 += v1; v1 = rotl32(v1, r[i]); v1 ^= v0; }
        v0 += ks[(g + 1) % 3];
        v1 += ks[(g + 2) % 3] + (uint32_t)(g + 1);
    }
    *o0 = v0; *o1 = v1;
}

extern "C" void kernel_launch(void* const* d_in, const int* in_sizes, int n_in,
                              void* d_out, int out_size) {
    const float* x = (const float*)d_in[0];
    float* out = (float*)d_out;
    int n = in_sizes[0];

    InitIdx p;
    {
        uint32_t span = (uint32_t)n;
        uint32_t k1a, k1b, k2a, k2b;
        tf2x32(0u, 42u, 0u, 0u, &k1a, &k1b);
        tf2x32(0u, 42u, 0u, 1u, &k2a, &k2b);
        uint32_t m1 = 65536u % span;
        uint32_t mult = ((uint32_t)(m1 * m1)) % span;
        for (int i = 0; i < KC; i++) {
            uint32_t h1, h2, l1, l2;
            tf2x32(k1a, k1b, 0u, (uint32_t)i, &h1, &h2);
            tf2x32(k2a, k2b, 0u, (uint32_t)i, &l1, &l2);
            uint32_t hb = h1 ^ h2, lb = l1 ^ l2;
            uint32_t off = ((uint32_t)((hb % span) * mult) + (lb % span)) % span;
            p.idx[i] = (int)off;
        }
    }

    k_clear<<<1024, 256>>>();
    k_hist<<<2048, 256>>>(x, n);
    k_scanA<<<SCB, 256>>>();
    k_scanB<<<1, 1024>>>();
    k_scanC<<<SCB, 256>>>();
    k_scatter<<<2048, 256>>>(x, n);
    k_init<<<1, 256>>>(x, p);
    for (int it = 0; it < 10; it++) {
        k_prep<<<1, 256>>>(it > 0 ? 1 : 0, n);
        k_bnd<<<KC - 1, 128>>>();
    }
    k_prep<<<1, 256>>>(1, n);
    k_out<<<1024, 256>>>(x, out, n);
}